// round 2
// baseline (speedup 1.0000x reference)
#include <cuda_runtime.h>
#include <math.h>

// Problem constants
#define MM    96      // MMAX
#define LLM   96      // LMAX
#define TLAT  255     // NLAT = 4*64-1
#define BC    256     // B*C = 4*64
#define NPIX  49152   // 12 * 64^2
#define BCC   8       // bc values per block

// Scratch: phase-rotated spectral coefficients, pre-scaled by 2 (irfft weight).
// Layout [bc][m][t] so kernel A stores are coalesced along t(=k).
__device__ float g_re[BC * MM * TLAT];
__device__ float g_im[BC * MM * TLAT];

// ---------------------------------------------------------------------------
// Kernel A: rl[bc,k,m] = sum_l x[bc,l,m] * pct[m,l,k], then multiply by
// exp(i*offset[k,m]), scale by 2, store to g_re/g_im in [bc][m][k] layout.
// Grid: (m=96, bcChunk=32), Block: 256 threads (thread = k ring index).
// ---------------------------------------------------------------------------
__global__ __launch_bounds__(256)
void legendre_phase_kernel(const float* __restrict__ xr,
                           const float* __restrict__ xi,
                           const float* __restrict__ pct,
                           const float* __restrict__ off)
{
    const int m   = blockIdx.x;       // 0..95
    const int bc0 = blockIdx.y * BCC; // 0,8,...,248
    const int k   = threadIdx.x;      // 0..255 (255 active rings)

    __shared__ __align__(16) float sr[LLM * BCC];
    __shared__ __align__(16) float si[LLM * BCC];

    // Stage x_real/x_imag slices: s[l][b] = x[(bc0+b), l, m]
    for (int idx = threadIdx.x; idx < LLM * BCC; idx += 256) {
        const int l = idx >> 3;
        const int b = idx & 7;
        const int g = ((bc0 + b) * LLM + l) * MM + m;
        sr[idx] = xr[g];
        si[idx] = xi[g];
    }
    __syncthreads();

    if (k >= TLAT) return;

    float ar0=0.f, ar1=0.f, ar2=0.f, ar3=0.f, ar4=0.f, ar5=0.f, ar6=0.f, ar7=0.f;
    float ai0=0.f, ai1=0.f, ai2=0.f, ai3=0.f, ai4=0.f, ai5=0.f, ai6=0.f, ai7=0.f;

    const float* __restrict__ pm = pct + (size_t)m * LLM * TLAT + k;

    #pragma unroll 4
    for (int l = 0; l < LLM; ++l) {
        const float p = pm[(size_t)l * TLAT];            // coalesced across k
        const float4 rA = *(const float4*)(sr + l * BCC);
        const float4 rB = *(const float4*)(sr + l * BCC + 4);
        const float4 iA = *(const float4*)(si + l * BCC);
        const float4 iB = *(const float4*)(si + l * BCC + 4);
        ar0 = fmaf(rA.x, p, ar0); ai0 = fmaf(iA.x, p, ai0);
        ar1 = fmaf(rA.y, p, ar1); ai1 = fmaf(iA.y, p, ai1);
        ar2 = fmaf(rA.z, p, ar2); ai2 = fmaf(iA.z, p, ai2);
        ar3 = fmaf(rA.w, p, ar3); ai3 = fmaf(iA.w, p, ai3);
        ar4 = fmaf(rB.x, p, ar4); ai4 = fmaf(iB.x, p, ai4);
        ar5 = fmaf(rB.y, p, ar5); ai5 = fmaf(iB.y, p, ai5);
        ar6 = fmaf(rB.z, p, ar6); ai6 = fmaf(iB.z, p, ai6);
        ar7 = fmaf(rB.w, p, ar7); ai7 = fmaf(iB.w, p, ai7);
    }

    float sa, ca;
    sincosf(off[k * MM + m], &sa, &ca);

    // store 2*( (ar + i*ai) * (ca + i*sa) )
    #define STORE_ONE(b, AR, AI)                                            \
    {                                                                       \
        const float vr = AR * ca - AI * sa;                                 \
        const float vi = AR * sa + AI * ca;                                 \
        const size_t o = ((size_t)(bc0 + b) * MM + m) * TLAT + k;           \
        g_re[o] = 2.0f * vr;                                                \
        g_im[o] = 2.0f * vi;                                                \
    }
    STORE_ONE(0, ar0, ai0) STORE_ONE(1, ar1, ai1)
    STORE_ONE(2, ar2, ai2) STORE_ONE(3, ar3, ai3)
    STORE_ONE(4, ar4, ai4) STORE_ONE(5, ar5, ai5)
    STORE_ONE(6, ar6, ai6) STORE_ONE(7, ar7, ai7)
    #undef STORE_ONE
}

// ---------------------------------------------------------------------------
// Kernel B: per-ring inverse real DFT (norm='forward', even n).
//   y[j] = Xr[0] + 2*sum_{k=1}^{kend}(Xr[k] cos(k*phi) - Xi[k] sin(k*phi))
//          + (n/2<96 ? (-1)^j * Xr[n/2] : 0),   phi = 2*pi*j/n
// Stored coefficients are pre-scaled by 2, so bin0/edge use factor 0.5.
// Grid: (bcChunk=32, t=255), Block: 256 threads (thread = longitude j).
// ---------------------------------------------------------------------------
__global__ __launch_bounds__(256)
void ring_idft_kernel(float* __restrict__ out)
{
    const int t   = blockIdx.y;
    const int bc0 = blockIdx.x * BCC;
    const int j   = threadIdx.x;

    // HEALPix ring geometry (nside = 64)
    int n, roff;
    if (t <= 62)       { n = 4 * (t + 1); roff = 2 * t * (t + 1); }
    else if (t <= 191) { n = 256;         roff = 8064 + 256 * (t - 63); }
    else               { const int w = 255 - t; n = 4 * w; roff = NPIX - 2 * w * (w + 1); }

    __shared__ __align__(16) float sr[MM * BCC];
    __shared__ __align__(16) float si[MM * BCC];

    for (int idx = threadIdx.x; idx < MM * BCC; idx += 256) {
        const int m = idx >> 3;
        const int b = idx & 7;
        const size_t g = ((size_t)(bc0 + b) * MM + m) * TLAT + t;
        sr[idx] = g_re[g];
        si[idx] = g_im[g];
    }
    __syncthreads();

    if (j >= n) return;

    const int nh   = n >> 1;
    const int kend = (nh - 1 < MM - 1) ? (nh - 1) : (MM - 1);

    // bin 0: weight 1 (stored x2 -> 0.5), real part only
    float a0, a1, a2, a3, a4, a5, a6, a7;
    {
        const float4 rA = *(const float4*)(sr);
        const float4 rB = *(const float4*)(sr + 4);
        a0 = 0.5f * rA.x; a1 = 0.5f * rA.y; a2 = 0.5f * rA.z; a3 = 0.5f * rA.w;
        a4 = 0.5f * rB.x; a5 = 0.5f * rB.y; a6 = 0.5f * rB.z; a7 = 0.5f * rB.w;
    }

    const float phi = 6.283185307179586f * (float)j / (float)n;
    float c1, s1;
    sincosf(phi, &s1, &c1);
    float c = c1, s = s1;

    for (int k = 1; k <= kend; ++k) {
        const float4 rA = *(const float4*)(sr + k * BCC);
        const float4 rB = *(const float4*)(sr + k * BCC + 4);
        const float4 iA = *(const float4*)(si + k * BCC);
        const float4 iB = *(const float4*)(si + k * BCC + 4);
        const float ns = -s;
        a0 = fmaf(iA.x, ns, fmaf(rA.x, c, a0));
        a1 = fmaf(iA.y, ns, fmaf(rA.y, c, a1));
        a2 = fmaf(iA.z, ns, fmaf(rA.z, c, a2));
        a3 = fmaf(iA.w, ns, fmaf(rA.w, c, a3));
        a4 = fmaf(iB.x, ns, fmaf(rB.x, c, a4));
        a5 = fmaf(iB.y, ns, fmaf(rB.y, c, a5));
        a6 = fmaf(iB.z, ns, fmaf(rB.z, c, a6));
        a7 = fmaf(iB.w, ns, fmaf(rB.w, c, a7));
        // rotate (c,s) by phi
        const float cn = fmaf(c, c1, -s * s1);
        const float sn = fmaf(s, c1,  c * s1);
        c = cn; s = sn;
    }

    // Nyquist bin n/2 (only if it exists within the 96 input bins):
    // weight 1 (stored x2 -> 0.5), real part, sign (-1)^j
    if (nh < MM) {
        const float sgn = (j & 1) ? -0.5f : 0.5f;
        const float4 rA = *(const float4*)(sr + nh * BCC);
        const float4 rB = *(const float4*)(sr + nh * BCC + 4);
        a0 = fmaf(sgn, rA.x, a0); a1 = fmaf(sgn, rA.y, a1);
        a2 = fmaf(sgn, rA.z, a2); a3 = fmaf(sgn, rA.w, a3);
        a4 = fmaf(sgn, rB.x, a4); a5 = fmaf(sgn, rB.y, a5);
        a6 = fmaf(sgn, rB.z, a6); a7 = fmaf(sgn, rB.w, a7);
    }

    const size_t ob = (size_t)bc0 * NPIX + roff + j;
    out[ob + 0 * (size_t)NPIX] = a0;
    out[ob + 1 * (size_t)NPIX] = a1;
    out[ob + 2 * (size_t)NPIX] = a2;
    out[ob + 3 * (size_t)NPIX] = a3;
    out[ob + 4 * (size_t)NPIX] = a4;
    out[ob + 5 * (size_t)NPIX] = a5;
    out[ob + 6 * (size_t)NPIX] = a6;
    out[ob + 7 * (size_t)NPIX] = a7;
}

// ---------------------------------------------------------------------------
extern "C" void kernel_launch(void* const* d_in, const int* in_sizes, int n_in,
                              void* d_out, int out_size)
{
    const float* xr  = (const float*)d_in[0];  // (4,64,96,96)
    const float* xi  = (const float*)d_in[1];  // (4,64,96,96)
    const float* pct = (const float*)d_in[2];  // (96,96,255)
    const float* off = (const float*)d_in[3];  // (255,96)
    float* out = (float*)d_out;                // (4,64,49152)

    {
        dim3 grid(MM, BC / BCC);   // 96 x 32
        legendre_phase_kernel<<<grid, 256>>>(xr, xi, pct, off);
    }
    {
        dim3 grid(BC / BCC, TLAT); // 32 x 255
        ring_idft_kernel<<<grid, 256>>>(out);
    }
}

// round 3
// speedup vs baseline: 1.4721x; 1.4721x over previous
#include <cuda_runtime.h>
#include <math.h>

// Problem constants
#define MM    96      // MMAX
#define LLM   96      // LMAX
#define TLAT  255     // NLAT = 4*64-1
#define BC    256     // B*C = 4*64
#define NPIX  49152   // 12 * 64^2
#define BCC   8       // bc values per block

// Scratch: phase-rotated spectral coefficients, pre-scaled by 2 (irfft weight).
// Layout [bc][m][t] so kernel A stores are coalesced along t(=k).
__device__ float g_re[BC * MM * TLAT];
__device__ float g_im[BC * MM * TLAT];

// ---------------------------------------------------------------------------
// Kernel A: rl[bc,k,m] = sum_l x[bc,l,m] * pct[m,l,k], then multiply by
// exp(i*offset[k,m]), scale by 2, store to g_re/g_im in [bc][m][k] layout.
// Each thread computes TWO rings (k, k+128) so each smem float4 feeds 32 FMA.
// Grid: (m=96, bcChunk=32), Block: 128 threads.
// ---------------------------------------------------------------------------
__global__ __launch_bounds__(128)
void legendre_phase_kernel(const float* __restrict__ xr,
                           const float* __restrict__ xi,
                           const float* __restrict__ pct,
                           const float* __restrict__ off)
{
    const int m   = blockIdx.x;       // 0..95
    const int bc0 = blockIdx.y * BCC; // 0,8,...,248
    const int kA  = threadIdx.x;      // ring 1: 0..127
    const int kBr = kA + 128;         // ring 2: 128..255
    const bool has2 = (kBr < TLAT);
    const int kB  = has2 ? kBr : (TLAT - 1);   // clamped (result discarded)

    __shared__ __align__(16) float sr[LLM * BCC];
    __shared__ __align__(16) float si[LLM * BCC];

    // Stage x_real/x_imag slices: s[l][b] = x[(bc0+b), l, m]
    for (int idx = threadIdx.x; idx < LLM * BCC; idx += 128) {
        const int l = idx >> 3;
        const int b = idx & 7;
        const int g = ((bc0 + b) * LLM + l) * MM + m;
        sr[idx] = xr[g];
        si[idx] = xi[g];
    }
    __syncthreads();

    float ar[8], ai[8], br[8], bi[8];
    #pragma unroll
    for (int b = 0; b < 8; ++b) { ar[b]=0.f; ai[b]=0.f; br[b]=0.f; bi[b]=0.f; }

    const float* __restrict__ pm = pct + (size_t)m * LLM * TLAT;

    #pragma unroll 4
    for (int l = 0; l < LLM; ++l) {
        const float pA = pm[(size_t)l * TLAT + kA];   // coalesced across threads
        const float pB = pm[(size_t)l * TLAT + kB];
        const float4 rA = *(const float4*)(sr + l * BCC);
        const float4 rB = *(const float4*)(sr + l * BCC + 4);
        const float4 iA = *(const float4*)(si + l * BCC);
        const float4 iB = *(const float4*)(si + l * BCC + 4);
        ar[0]=fmaf(rA.x,pA,ar[0]); ai[0]=fmaf(iA.x,pA,ai[0]); br[0]=fmaf(rA.x,pB,br[0]); bi[0]=fmaf(iA.x,pB,bi[0]);
        ar[1]=fmaf(rA.y,pA,ar[1]); ai[1]=fmaf(iA.y,pA,ai[1]); br[1]=fmaf(rA.y,pB,br[1]); bi[1]=fmaf(iA.y,pB,bi[1]);
        ar[2]=fmaf(rA.z,pA,ar[2]); ai[2]=fmaf(iA.z,pA,ai[2]); br[2]=fmaf(rA.z,pB,br[2]); bi[2]=fmaf(iA.z,pB,bi[2]);
        ar[3]=fmaf(rA.w,pA,ar[3]); ai[3]=fmaf(iA.w,pA,ai[3]); br[3]=fmaf(rA.w,pB,br[3]); bi[3]=fmaf(iA.w,pB,bi[3]);
        ar[4]=fmaf(rB.x,pA,ar[4]); ai[4]=fmaf(iB.x,pA,ai[4]); br[4]=fmaf(rB.x,pB,br[4]); bi[4]=fmaf(iB.x,pB,bi[4]);
        ar[5]=fmaf(rB.y,pA,ar[5]); ai[5]=fmaf(iB.y,pA,ai[5]); br[5]=fmaf(rB.y,pB,br[5]); bi[5]=fmaf(iB.y,pB,bi[5]);
        ar[6]=fmaf(rB.z,pA,ar[6]); ai[6]=fmaf(iB.z,pA,ai[6]); br[6]=fmaf(rB.z,pB,br[6]); bi[6]=fmaf(iB.z,pB,bi[6]);
        ar[7]=fmaf(rB.w,pA,ar[7]); ai[7]=fmaf(iB.w,pA,ai[7]); br[7]=fmaf(rB.w,pB,br[7]); bi[7]=fmaf(iB.w,pB,bi[7]);
    }

    float saA, caA, saB, caB;
    sincosf(off[kA * MM + m], &saA, &caA);
    sincosf(off[kB * MM + m], &saB, &caB);

    #pragma unroll
    for (int b = 0; b < 8; ++b) {
        const size_t oA = ((size_t)(bc0 + b) * MM + m) * TLAT + kA;
        g_re[oA] = 2.0f * (ar[b] * caA - ai[b] * saA);
        g_im[oA] = 2.0f * (ar[b] * saA + ai[b] * caA);
        if (has2) {
            const size_t oB = ((size_t)(bc0 + b) * MM + m) * TLAT + kB;
            g_re[oB] = 2.0f * (br[b] * caB - bi[b] * saB);
            g_im[oB] = 2.0f * (br[b] * saB + bi[b] * caB);
        }
    }
}

// ---------------------------------------------------------------------------
// Kernel B: per-ring inverse real DFT (norm='forward', even n).
// Output pairing: thread j in [0, n/2) produces y[j] and y[j+n/2] via
// even/odd-k accumulator split (cos(k(phi+pi)) = (-1)^k cos(k phi)):
//   y[j]      = E + O + nyq(j)
//   y[j+n/2]  = E - O + nyq(j+n/2)
// Stored coefficients are pre-scaled by 2, so bin0/Nyquist use factor 0.5.
// Grid: (bcChunk=32, t=255), Block: 128 threads.
// ---------------------------------------------------------------------------
__global__ __launch_bounds__(128)
void ring_idft_kernel(float* __restrict__ out)
{
    const int t   = blockIdx.y;
    const int bc0 = blockIdx.x * BCC;
    const int j   = threadIdx.x;

    // HEALPix ring geometry (nside = 64)
    int n, roff;
    if (t <= 62)       { n = 4 * (t + 1); roff = 2 * t * (t + 1); }
    else if (t <= 191) { n = 256;         roff = 8064 + 256 * (t - 63); }
    else               { const int w = 255 - t; n = 4 * w; roff = NPIX - 2 * w * (w + 1); }

    const int nh   = n >> 1;
    const int kend = (nh - 1 < MM - 1) ? (nh - 1) : (MM - 1);
    const int kmax = (nh < MM - 1) ? nh : (MM - 1);   // highest bin we touch

    __shared__ __align__(16) float sr[MM * BCC];
    __shared__ __align__(16) float si[MM * BCC];

    for (int idx = threadIdx.x; idx < (kmax + 1) * BCC; idx += 128) {
        const int m = idx >> 3;
        const int b = idx & 7;
        const size_t g = ((size_t)(bc0 + b) * MM + m) * TLAT + t;
        sr[idx] = g_re[g];
        si[idx] = g_im[g];
    }
    __syncthreads();

    if (j >= nh) return;

    // Even-k accumulator E gets bin 0 (weight 1; stored x2 -> 0.5), real only.
    float e0,e1,e2,e3,e4,e5,e6,e7;
    float o0,o1,o2,o3,o4,o5,o6,o7;
    {
        const float4 rA = *(const float4*)(sr);
        const float4 rB = *(const float4*)(sr + 4);
        e0 = 0.5f*rA.x; e1 = 0.5f*rA.y; e2 = 0.5f*rA.z; e3 = 0.5f*rA.w;
        e4 = 0.5f*rB.x; e5 = 0.5f*rB.y; e6 = 0.5f*rB.z; e7 = 0.5f*rB.w;
    }
    o0=o1=o2=o3=o4=o5=o6=o7=0.f;

    const float phi = 6.283185307179586f * (float)j / (float)n;
    float c1, s1;
    sincosf(phi, &s1, &c1);
    float c = c1, s = s1;   // twiddle for k=1

    #define ACC_K(KIDX, CC, SS, A0,A1,A2,A3,A4,A5,A6,A7)                    \
    {                                                                       \
        const float4 rA = *(const float4*)(sr + (KIDX) * BCC);              \
        const float4 rB = *(const float4*)(sr + (KIDX) * BCC + 4);          \
        const float4 iA = *(const float4*)(si + (KIDX) * BCC);              \
        const float4 iB = *(const float4*)(si + (KIDX) * BCC + 4);          \
        const float ns = -(SS);                                             \
        A0 = fmaf(iA.x, ns, fmaf(rA.x, (CC), A0));                          \
        A1 = fmaf(iA.y, ns, fmaf(rA.y, (CC), A1));                          \
        A2 = fmaf(iA.z, ns, fmaf(rA.z, (CC), A2));                          \
        A3 = fmaf(iA.w, ns, fmaf(rA.w, (CC), A3));                          \
        A4 = fmaf(iB.x, ns, fmaf(rB.x, (CC), A4));                          \
        A5 = fmaf(iB.y, ns, fmaf(rB.y, (CC), A5));                          \
        A6 = fmaf(iB.z, ns, fmaf(rB.z, (CC), A6));                          \
        A7 = fmaf(iB.w, ns, fmaf(rB.w, (CC), A7));                          \
    }

    int k = 1;
    for (; k + 1 <= kend; k += 2) {
        // odd k -> O with (c, s)
        ACC_K(k, c, s, o0,o1,o2,o3,o4,o5,o6,o7)
        // advance twiddle to k+1
        const float c2 = fmaf(c, c1, -s * s1);
        const float s2 = fmaf(s, c1,  c * s1);
        // even k+1 -> E with (c2, s2)
        ACC_K(k + 1, c2, s2, e0,e1,e2,e3,e4,e5,e6,e7)
        // advance twiddle to k+2
        c = fmaf(c2, c1, -s2 * s1);
        s = fmaf(s2, c1,  c2 * s1);
    }
    if (k == kend) {   // leftover odd k
        ACC_K(k, c, s, o0,o1,o2,o3,o4,o5,o6,o7)
    }
    #undef ACC_K

    float y0 = e0 + o0, y1 = e1 + o1, y2 = e2 + o2, y3 = e3 + o3;
    float y4 = e4 + o4, y5 = e5 + o5, y6 = e6 + o6, y7 = e7 + o7;
    float z0 = e0 - o0, z1 = e1 - o1, z2 = e2 - o2, z3 = e3 - o3;
    float z4 = e4 - o4, z5 = e5 - o5, z6 = e6 - o6, z7 = e7 - o7;

    // Nyquist bin n/2 (exists within 96 input bins only when nh < 96):
    // weight 1 (stored x2 -> 0.5), real part, sign (-1)^j
    if (nh < MM) {
        const float sgA = (j & 1) ? -0.5f : 0.5f;
        const float sgB = (nh & 1) ? -sgA : sgA;   // sign at j+nh
        const float4 rA = *(const float4*)(sr + nh * BCC);
        const float4 rB = *(const float4*)(sr + nh * BCC + 4);
        y0 = fmaf(sgA, rA.x, y0); z0 = fmaf(sgB, rA.x, z0);
        y1 = fmaf(sgA, rA.y, y1); z1 = fmaf(sgB, rA.y, z1);
        y2 = fmaf(sgA, rA.z, y2); z2 = fmaf(sgB, rA.z, z2);
        y3 = fmaf(sgA, rA.w, y3); z3 = fmaf(sgB, rA.w, z3);
        y4 = fmaf(sgA, rB.x, y4); z4 = fmaf(sgB, rB.x, z4);
        y5 = fmaf(sgA, rB.y, y5); z5 = fmaf(sgB, rB.y, z5);
        y6 = fmaf(sgA, rB.z, y6); z6 = fmaf(sgB, rB.z, z6);
        y7 = fmaf(sgA, rB.w, y7); z7 = fmaf(sgB, rB.w, z7);
    }

    const size_t ob = (size_t)bc0 * NPIX + roff + j;
    out[ob + 0*(size_t)NPIX] = y0;  out[ob + 0*(size_t)NPIX + nh] = z0;
    out[ob + 1*(size_t)NPIX] = y1;  out[ob + 1*(size_t)NPIX + nh] = z1;
    out[ob + 2*(size_t)NPIX] = y2;  out[ob + 2*(size_t)NPIX + nh] = z2;
    out[ob + 3*(size_t)NPIX] = y3;  out[ob + 3*(size_t)NPIX + nh] = z3;
    out[ob + 4*(size_t)NPIX] = y4;  out[ob + 4*(size_t)NPIX + nh] = z4;
    out[ob + 5*(size_t)NPIX] = y5;  out[ob + 5*(size_t)NPIX + nh] = z5;
    out[ob + 6*(size_t)NPIX] = y6;  out[ob + 6*(size_t)NPIX + nh] = z6;
    out[ob + 7*(size_t)NPIX] = y7;  out[ob + 7*(size_t)NPIX + nh] = z7;
}

// ---------------------------------------------------------------------------
extern "C" void kernel_launch(void* const* d_in, const int* in_sizes, int n_in,
                              void* d_out, int out_size)
{
    const float* xr  = (const float*)d_in[0];  // (4,64,96,96)
    const float* xi  = (const float*)d_in[1];  // (4,64,96,96)
    const float* pct = (const float*)d_in[2];  // (96,96,255)
    const float* off = (const float*)d_in[3];  // (255,96)
    float* out = (float*)d_out;                // (4,64,49152)

    {
        dim3 grid(MM, BC / BCC);   // 96 x 32
        legendre_phase_kernel<<<grid, 128>>>(xr, xi, pct, off);
    }
    {
        dim3 grid(BC / BCC, TLAT); // 32 x 255
        ring_idft_kernel<<<grid, 128>>>(out);
    }
}

// round 4
// speedup vs baseline: 1.6967x; 1.1526x over previous
#include <cuda_runtime.h>
#include <math.h>

// Problem constants
#define MM    96      // MMAX
#define LLM   96      // LMAX
#define TLAT  255     // NLAT = 4*64-1
#define BC    256     // B*C = 4*64
#define NPIX  49152   // 12 * 64^2
#define BCC   8       // bc values per block

// Scratch: phase-rotated spectral coefficients, pre-scaled by 2 (irfft weight).
// Layout [bc][m][t] so kernel A stores are coalesced along t(=k).
__device__ float g_re[BC * MM * TLAT];
__device__ float g_im[BC * MM * TLAT];

// ---------------------------------------------------------------------------
// Kernel A: rl[bc,k,m] = sum_l x[bc,l,m] * pct[m,l,k], then multiply by
// exp(i*offset[k,m]), scale by 2, store to g_re/g_im in [bc][m][k] layout.
// Each thread computes TWO rings (k, k+128) so each smem float4 feeds 32 FMA.
// Grid: (m=96, bcChunk=32), Block: 128 threads.
// ---------------------------------------------------------------------------
__global__ __launch_bounds__(128)
void legendre_phase_kernel(const float* __restrict__ xr,
                           const float* __restrict__ xi,
                           const float* __restrict__ pct,
                           const float* __restrict__ off)
{
    const int m   = blockIdx.x;       // 0..95
    const int bc0 = blockIdx.y * BCC; // 0,8,...,248
    const int kA  = threadIdx.x;      // ring 1: 0..127
    const int kBr = kA + 128;         // ring 2: 128..255
    const bool has2 = (kBr < TLAT);
    const int kB  = has2 ? kBr : (TLAT - 1);   // clamped (result discarded)

    __shared__ __align__(16) float sr[LLM * BCC];
    __shared__ __align__(16) float si[LLM * BCC];

    // Stage x_real/x_imag slices: s[l][b] = x[(bc0+b), l, m]
    for (int idx = threadIdx.x; idx < LLM * BCC; idx += 128) {
        const int l = idx >> 3;
        const int b = idx & 7;
        const int g = ((bc0 + b) * LLM + l) * MM + m;
        sr[idx] = xr[g];
        si[idx] = xi[g];
    }
    __syncthreads();

    float ar[8], ai[8], br[8], bi[8];
    #pragma unroll
    for (int b = 0; b < 8; ++b) { ar[b]=0.f; ai[b]=0.f; br[b]=0.f; bi[b]=0.f; }

    const float* __restrict__ pm = pct + (size_t)m * LLM * TLAT;

    #pragma unroll 4
    for (int l = 0; l < LLM; ++l) {
        const float pA = pm[(size_t)l * TLAT + kA];   // coalesced across threads
        const float pB = pm[(size_t)l * TLAT + kB];
        const float4 rA = *(const float4*)(sr + l * BCC);
        const float4 rB = *(const float4*)(sr + l * BCC + 4);
        const float4 iA = *(const float4*)(si + l * BCC);
        const float4 iB = *(const float4*)(si + l * BCC + 4);
        ar[0]=fmaf(rA.x,pA,ar[0]); ai[0]=fmaf(iA.x,pA,ai[0]); br[0]=fmaf(rA.x,pB,br[0]); bi[0]=fmaf(iA.x,pB,bi[0]);
        ar[1]=fmaf(rA.y,pA,ar[1]); ai[1]=fmaf(iA.y,pA,ai[1]); br[1]=fmaf(rA.y,pB,br[1]); bi[1]=fmaf(iA.y,pB,bi[1]);
        ar[2]=fmaf(rA.z,pA,ar[2]); ai[2]=fmaf(iA.z,pA,ai[2]); br[2]=fmaf(rA.z,pB,br[2]); bi[2]=fmaf(iA.z,pB,bi[2]);
        ar[3]=fmaf(rA.w,pA,ar[3]); ai[3]=fmaf(iA.w,pA,ai[3]); br[3]=fmaf(rA.w,pB,br[3]); bi[3]=fmaf(iA.w,pB,bi[3]);
        ar[4]=fmaf(rB.x,pA,ar[4]); ai[4]=fmaf(iB.x,pA,ai[4]); br[4]=fmaf(rB.x,pB,br[4]); bi[4]=fmaf(iB.x,pB,bi[4]);
        ar[5]=fmaf(rB.y,pA,ar[5]); ai[5]=fmaf(iB.y,pA,ai[5]); br[5]=fmaf(rB.y,pB,br[5]); bi[5]=fmaf(iB.y,pB,bi[5]);
        ar[6]=fmaf(rB.z,pA,ar[6]); ai[6]=fmaf(iB.z,pA,ai[6]); br[6]=fmaf(rB.z,pB,br[6]); bi[6]=fmaf(iB.z,pB,bi[6]);
        ar[7]=fmaf(rB.w,pA,ar[7]); ai[7]=fmaf(iB.w,pA,ai[7]); br[7]=fmaf(rB.w,pB,br[7]); bi[7]=fmaf(iB.w,pB,bi[7]);
    }

    float saA, caA, saB, caB;
    sincosf(off[kA * MM + m], &saA, &caA);
    sincosf(off[kB * MM + m], &saB, &caB);

    #pragma unroll
    for (int b = 0; b < 8; ++b) {
        const size_t oA = ((size_t)(bc0 + b) * MM + m) * TLAT + kA;
        g_re[oA] = 2.0f * (ar[b] * caA - ai[b] * saA);
        g_im[oA] = 2.0f * (ar[b] * saA + ai[b] * caA);
        if (has2) {
            const size_t oB = ((size_t)(bc0 + b) * MM + m) * TLAT + kB;
            g_re[oB] = 2.0f * (br[b] * caB - bi[b] * saB);
            g_im[oB] = 2.0f * (br[b] * saB + bi[b] * caB);
        }
    }
}

// ---------------------------------------------------------------------------
// Kernel B: per-ring inverse real DFT (norm='forward', even n, n % 4 == 0).
// Quarter-wave split: thread j in [0, n/4) produces the 4 outputs
// p = j + q*(n/4), q=0..3, using e^{ik*2pi*p/n} = e^{ik*phi} * i^{kq}.
// Per residue r = k mod 4 accumulate U_r = sum u_k, and V_r (odd r only),
// where u_k = Re[X~_k e^{ik phi}], v_k = Im[X~_k e^{ik phi}]:
//   y(j)        = (U0+U2) + (U1+U3)
//   y(j+n/4)    = (U0-U2) - (V1-V3)
//   y(j+n/2)    = (U0+U2) - (U1+U3)
//   y(j+3n/4)   = (U0-U2) + (V1-V3)
// Stored coefficients are pre-scaled by 2, so bin0/Nyquist use factor 0.5.
// Grid: (bcChunk=32, t=255), Block: 64 threads (n/4 <= 64 for every ring).
// ---------------------------------------------------------------------------
__global__ __launch_bounds__(64)
void ring_idft_kernel(float* __restrict__ out)
{
    const int t   = blockIdx.y;
    const int bc0 = blockIdx.x * BCC;
    const int j   = threadIdx.x;

    // HEALPix ring geometry (nside = 64)
    int n, roff;
    if (t <= 62)       { n = 4 * (t + 1); roff = 2 * t * (t + 1); }
    else if (t <= 191) { n = 256;         roff = 8064 + 256 * (t - 63); }
    else               { const int w = 255 - t; n = 4 * w; roff = NPIX - 2 * w * (w + 1); }

    const int nh   = n >> 1;
    const int n4   = n >> 2;
    const int kend = (nh - 1 < MM - 1) ? (nh - 1) : (MM - 1);
    const int kmax = (nh < MM - 1) ? nh : (MM - 1);   // highest bin we touch

    __shared__ __align__(16) float sr[MM * BCC];
    __shared__ __align__(16) float si[MM * BCC];

    for (int idx = threadIdx.x; idx < (kmax + 1) * BCC; idx += 64) {
        const int m = idx >> 3;
        const int b = idx & 7;
        const size_t g = ((size_t)(bc0 + b) * MM + m) * TLAT + t;
        sr[idx] = g_re[g];
        si[idx] = g_im[g];
    }
    __syncthreads();

    if (j >= n4) return;

    // Residue accumulators (8 bc lanes each)
    float U0[8], U1[8], U2[8], U3[8], V1[8], V3[8];
    // k=0 (bin 0): real only, weight 1 (stored x2 -> 0.5) -> U0
    {
        const float4 rA = *(const float4*)(sr);
        const float4 rB = *(const float4*)(sr + 4);
        U0[0]=0.5f*rA.x; U0[1]=0.5f*rA.y; U0[2]=0.5f*rA.z; U0[3]=0.5f*rA.w;
        U0[4]=0.5f*rB.x; U0[5]=0.5f*rB.y; U0[6]=0.5f*rB.z; U0[7]=0.5f*rB.w;
    }
    #pragma unroll
    for (int b = 0; b < 8; ++b) { U1[b]=0.f; U2[b]=0.f; U3[b]=0.f; V1[b]=0.f; V3[b]=0.f; }

    const float phi = 6.283185307179586f * (float)j / (float)n;
    float c1, s1;
    sincosf(phi, &s1, &c1);
    float c = c1, s = s1;   // twiddle for k=1

    // u accumulate only: U += Xr*c - Xi*s
    #define ACC_U(KIDX, UA)                                                 \
    {                                                                       \
        const float4 rA = *(const float4*)(sr + (KIDX) * BCC);              \
        const float4 rB = *(const float4*)(sr + (KIDX) * BCC + 4);          \
        const float4 iA = *(const float4*)(si + (KIDX) * BCC);              \
        const float4 iB = *(const float4*)(si + (KIDX) * BCC + 4);          \
        UA[0]=fmaf(rA.x,c,fmaf(iA.x,-s,UA[0]));                             \
        UA[1]=fmaf(rA.y,c,fmaf(iA.y,-s,UA[1]));                             \
        UA[2]=fmaf(rA.z,c,fmaf(iA.z,-s,UA[2]));                             \
        UA[3]=fmaf(rA.w,c,fmaf(iA.w,-s,UA[3]));                             \
        UA[4]=fmaf(rB.x,c,fmaf(iB.x,-s,UA[4]));                             \
        UA[5]=fmaf(rB.y,c,fmaf(iB.y,-s,UA[5]));                             \
        UA[6]=fmaf(rB.z,c,fmaf(iB.z,-s,UA[6]));                             \
        UA[7]=fmaf(rB.w,c,fmaf(iB.w,-s,UA[7]));                             \
    }
    // u and v accumulate: U += Xr*c - Xi*s ; V += Xr*s + Xi*c
    #define ACC_UV(KIDX, UA, VA)                                            \
    {                                                                       \
        const float4 rA = *(const float4*)(sr + (KIDX) * BCC);              \
        const float4 rB = *(const float4*)(sr + (KIDX) * BCC + 4);          \
        const float4 iA = *(const float4*)(si + (KIDX) * BCC);              \
        const float4 iB = *(const float4*)(si + (KIDX) * BCC + 4);          \
        UA[0]=fmaf(rA.x,c,fmaf(iA.x,-s,UA[0])); VA[0]=fmaf(rA.x,s,fmaf(iA.x,c,VA[0])); \
        UA[1]=fmaf(rA.y,c,fmaf(iA.y,-s,UA[1])); VA[1]=fmaf(rA.y,s,fmaf(iA.y,c,VA[1])); \
        UA[2]=fmaf(rA.z,c,fmaf(iA.z,-s,UA[2])); VA[2]=fmaf(rA.z,s,fmaf(iA.z,c,VA[2])); \
        UA[3]=fmaf(rA.w,c,fmaf(iA.w,-s,UA[3])); VA[3]=fmaf(rA.w,s,fmaf(iA.w,c,VA[3])); \
        UA[4]=fmaf(rB.x,c,fmaf(iB.x,-s,UA[4])); VA[4]=fmaf(rB.x,s,fmaf(iB.x,c,VA[4])); \
        UA[5]=fmaf(rB.y,c,fmaf(iB.y,-s,UA[5])); VA[5]=fmaf(rB.y,s,fmaf(iB.y,c,VA[5])); \
        UA[6]=fmaf(rB.z,c,fmaf(iB.z,-s,UA[6])); VA[6]=fmaf(rB.z,s,fmaf(iB.z,c,VA[6])); \
        UA[7]=fmaf(rB.w,c,fmaf(iB.w,-s,UA[7])); VA[7]=fmaf(rB.w,s,fmaf(iB.w,c,VA[7])); \
    }
    #define ROT()                                                           \
    {                                                                       \
        const float cn = fmaf(c, c1, -s * s1);                              \
        const float sn = fmaf(s, c1,  c * s1);                              \
        c = cn; s = sn;                                                     \
    }

    int k = 1;
    for (; k + 3 <= kend; k += 4) {          // residues 1,2,3,0
        ACC_UV(k,     U1, V1) ROT()
        ACC_U (k + 1, U2)     ROT()
        ACC_UV(k + 2, U3, V3) ROT()
        ACC_U (k + 3, U0)     ROT()
    }
    for (; k <= kend; ++k) {                 // leftover 0-3 bins
        const int r = k & 3;
        if (r == 1)      { ACC_UV(k, U1, V1) }
        else if (r == 2) { ACC_U (k, U2)     }
        else if (r == 3) { ACC_UV(k, U3, V3) }
        else             { ACC_U (k, U0)     }
        ROT()
    }
    #undef ACC_U
    #undef ACC_UV
    #undef ROT

    // Nyquist bin n/2 (exists within 96 input bins only when nh < 96):
    // contributes sgn(p) * 0.5 * Xr[nh] at output p, sgn(p) = (-1)^p.
    float w0 = 0.f, w1 = 0.f, w2 = 0.f, w3 = 0.f, w4 = 0.f, w5 = 0.f, w6 = 0.f, w7 = 0.f;
    if (nh < MM) {
        const float4 rA = *(const float4*)(sr + nh * BCC);
        const float4 rB = *(const float4*)(sr + nh * BCC + 4);
        w0 = 0.5f*rA.x; w1 = 0.5f*rA.y; w2 = 0.5f*rA.z; w3 = 0.5f*rA.w;
        w4 = 0.5f*rB.x; w5 = 0.5f*rB.y; w6 = 0.5f*rB.z; w7 = 0.5f*rB.w;
    }

    const size_t ob = (size_t)bc0 * NPIX + roff + j;
    #pragma unroll
    for (int q = 0; q < 4; ++q) {
        const int p = j + q * n4;
        const float sg = (p & 1) ? -1.0f : 1.0f;
        float y[8];
        if (q == 0) {
            y[0]=(U0[0]+U2[0])+(U1[0]+U3[0]); y[1]=(U0[1]+U2[1])+(U1[1]+U3[1]);
            y[2]=(U0[2]+U2[2])+(U1[2]+U3[2]); y[3]=(U0[3]+U2[3])+(U1[3]+U3[3]);
            y[4]=(U0[4]+U2[4])+(U1[4]+U3[4]); y[5]=(U0[5]+U2[5])+(U1[5]+U3[5]);
            y[6]=(U0[6]+U2[6])+(U1[6]+U3[6]); y[7]=(U0[7]+U2[7])+(U1[7]+U3[7]);
        } else if (q == 1) {
            y[0]=(U0[0]-U2[0])-(V1[0]-V3[0]); y[1]=(U0[1]-U2[1])-(V1[1]-V3[1]);
            y[2]=(U0[2]-U2[2])-(V1[2]-V3[2]); y[3]=(U0[3]-U2[3])-(V1[3]-V3[3]);
            y[4]=(U0[4]-U2[4])-(V1[4]-V3[4]); y[5]=(U0[5]-U2[5])-(V1[5]-V3[5]);
            y[6]=(U0[6]-U2[6])-(V1[6]-V3[6]); y[7]=(U0[7]-U2[7])-(V1[7]-V3[7]);
        } else if (q == 2) {
            y[0]=(U0[0]+U2[0])-(U1[0]+U3[0]); y[1]=(U0[1]+U2[1])-(U1[1]+U3[1]);
            y[2]=(U0[2]+U2[2])-(U1[2]+U3[2]); y[3]=(U0[3]+U2[3])-(U1[3]+U3[3]);
            y[4]=(U0[4]+U2[4])-(U1[4]+U3[4]); y[5]=(U0[5]+U2[5])-(U1[5]+U3[5]);
            y[6]=(U0[6]+U2[6])-(U1[6]+U3[6]); y[7]=(U0[7]+U2[7])-(U1[7]+U3[7]);
        } else {
            y[0]=(U0[0]-U2[0])+(V1[0]-V3[0]); y[1]=(U0[1]-U2[1])+(V1[1]-V3[1]);
            y[2]=(U0[2]-U2[2])+(V1[2]-V3[2]); y[3]=(U0[3]-U2[3])+(V1[3]-V3[3]);
            y[4]=(U0[4]-U2[4])+(V1[4]-V3[4]); y[5]=(U0[5]-U2[5])+(V1[5]-V3[5]);
            y[6]=(U0[6]-U2[6])+(V1[6]-V3[6]); y[7]=(U0[7]-U2[7])+(V1[7]-V3[7]);
        }
        const size_t op = ob + (size_t)q * n4;
        out[op + 0*(size_t)NPIX] = fmaf(sg, w0, y[0]);
        out[op + 1*(size_t)NPIX] = fmaf(sg, w1, y[1]);
        out[op + 2*(size_t)NPIX] = fmaf(sg, w2, y[2]);
        out[op + 3*(size_t)NPIX] = fmaf(sg, w3, y[3]);
        out[op + 4*(size_t)NPIX] = fmaf(sg, w4, y[4]);
        out[op + 5*(size_t)NPIX] = fmaf(sg, w5, y[5]);
        out[op + 6*(size_t)NPIX] = fmaf(sg, w6, y[6]);
        out[op + 7*(size_t)NPIX] = fmaf(sg, w7, y[7]);
    }
}

// ---------------------------------------------------------------------------
extern "C" void kernel_launch(void* const* d_in, const int* in_sizes, int n_in,
                              void* d_out, int out_size)
{
    const float* xr  = (const float*)d_in[0];  // (4,64,96,96)
    const float* xi  = (const float*)d_in[1];  // (4,64,96,96)
    const float* pct = (const float*)d_in[2];  // (96,96,255)
    const float* off = (const float*)d_in[3];  // (255,96)
    float* out = (float*)d_out;                // (4,64,49152)

    {
        dim3 grid(MM, BC / BCC);   // 96 x 32
        legendre_phase_kernel<<<grid, 128>>>(xr, xi, pct, off);
    }
    {
        dim3 grid(BC / BCC, TLAT); // 32 x 255
        ring_idft_kernel<<<grid, 64>>>(out);
    }
}

// round 6
// speedup vs baseline: 1.7665x; 1.0412x over previous
#include <cuda_runtime.h>
#include <math.h>

// Problem constants
#define MM    96      // MMAX
#define LLM   96      // LMAX
#define TLAT  255     // NLAT = 4*64-1
#define BC    256     // B*C = 4*64
#define NPIX  49152   // 12 * 64^2

typedef unsigned long long ull;

// ---- f32x2 packed math helpers (Blackwell FFMA2) --------------------------
__device__ __forceinline__ ull pack2(float lo, float hi) {
    ull r; asm("mov.b64 %0, {%1, %2};" : "=l"(r) : "f"(lo), "f"(hi)); return r;
}
__device__ __forceinline__ void unpack2(ull v, float& lo, float& hi) {
    asm("mov.b64 {%0, %1}, %2;" : "=f"(lo), "=f"(hi) : "l"(v));
}
__device__ __forceinline__ ull fma2(ull a, ull b, ull c) {
    ull d; asm("fma.rn.f32x2 %0, %1, %2, %3;" : "=l"(d) : "l"(a), "l"(b), "l"(c)); return d;
}

// Scratch: phase-rotated spectral coefficients, pre-scaled by 2 (irfft weight).
// Layout [bc][m][t] so kernel A stores are coalesced along t(=k).
__device__ float g_re[BC * MM * TLAT];
__device__ float g_im[BC * MM * TLAT];

// ---------------------------------------------------------------------------
// Kernel A: rl[bc,k,m] = sum_l x[bc,l,m] * pct[m,l,k], then multiply by
// exp(i*offset[k,m]), scale by 2, store to g_re/g_im in [bc][m][k] layout.
// Each thread computes FOUR rings (k, k+64, k+128, k+192); smem holds (re,im)
// interleaved so one ulonglong2 load yields two f32x2 operands directly.
// Grid: (m=96, bcChunk=32), Block: 64 threads.  BCC = 8.
// ---------------------------------------------------------------------------
__global__ __launch_bounds__(64)
void legendre_phase_kernel(const float* __restrict__ xr,
                           const float* __restrict__ xi,
                           const float* __restrict__ pct,
                           const float* __restrict__ off)
{
    const int m   = blockIdx.x;
    const int bc0 = blockIdx.y * 8;
    const int tid = threadIdx.x;

    __shared__ __align__(16) float2 sx[LLM * 8];   // (re,im) pairs, [l][b]

    for (int idx = tid; idx < LLM * 8; idx += 64) {
        const int l = idx >> 3;
        const int b = idx & 7;
        const int g = ((bc0 + b) * LLM + l) * MM + m;
        sx[idx] = make_float2(xr[g], xi[g]);
    }
    __syncthreads();

    const int k0 = tid, k1 = tid + 64, k2 = tid + 128, k3r = tid + 192;
    const bool has3 = (k3r < TLAT);
    const int k3 = has3 ? k3r : (TLAT - 1);

    ull acc[4][8];
    #pragma unroll
    for (int q = 0; q < 4; ++q)
        #pragma unroll
        for (int b = 0; b < 8; ++b) acc[q][b] = 0ull;

    const float* __restrict__ pm = pct + (size_t)m * LLM * TLAT;

    #pragma unroll 2
    for (int l = 0; l < LLM; ++l) {
        const float* __restrict__ pr = pm + (size_t)l * TLAT;
        ull pp[4];
        pp[0] = pack2(pr[k0], pr[k0]);
        pp[1] = pack2(pr[k1], pr[k1]);
        pp[2] = pack2(pr[k2], pr[k2]);
        pp[3] = pack2(pr[k3], pr[k3]);
        const ulonglong2* __restrict__ row = (const ulonglong2*)(sx + l * 8);
        const ulonglong2 v0 = row[0];   // (re,im) for bc0, bc1
        const ulonglong2 v1 = row[1];   // bc2, bc3
        const ulonglong2 v2 = row[2];   // bc4, bc5
        const ulonglong2 v3 = row[3];   // bc6, bc7
        #pragma unroll
        for (int q = 0; q < 4; ++q) {
            acc[q][0] = fma2(v0.x, pp[q], acc[q][0]);
            acc[q][1] = fma2(v0.y, pp[q], acc[q][1]);
            acc[q][2] = fma2(v1.x, pp[q], acc[q][2]);
            acc[q][3] = fma2(v1.y, pp[q], acc[q][3]);
            acc[q][4] = fma2(v2.x, pp[q], acc[q][4]);
            acc[q][5] = fma2(v2.y, pp[q], acc[q][5]);
            acc[q][6] = fma2(v3.x, pp[q], acc[q][6]);
            acc[q][7] = fma2(v3.y, pp[q], acc[q][7]);
        }
    }

    const int kq[4] = { k0, k1, k2, k3 };
    #pragma unroll
    for (int q = 0; q < 4; ++q) {
        if (q == 3 && !has3) break;
        float sa, ca;
        sincosf(off[kq[q] * MM + m], &sa, &ca);
        #pragma unroll
        for (int b = 0; b < 8; ++b) {
            float ar, ai;
            unpack2(acc[q][b], ar, ai);
            const size_t o = ((size_t)(bc0 + b) * MM + m) * TLAT + kq[q];
            g_re[o] = 2.0f * (ar * ca - ai * sa);
            g_im[o] = 2.0f * (ar * sa + ai * ca);
        }
    }
}

// ---------------------------------------------------------------------------
// Kernel B: per-ring inverse real DFT (norm='forward', n % 4 == 0).
// Quarter-wave split + j-pairing: thread handles j0=2*tid and j1=j0+1, each
// producing 4 outputs p = j + q*(n/4) via residue accumulators:
//   y(j)      = (U0+U2) + (U1+U3)
//   y(j+n/4)  = (U0-U2) - (V1-V3)
//   y(j+n/2)  = (U0+U2) - (U1+U3)
//   y(j+3n/4) = (U0-U2) + (V1-V3)
// BCC = 4 bc lanes per block, packed as two f32x2 pairs.
// Stored coefficients pre-scaled by 2, so bin0/Nyquist use factor 0.5.
// Grid: (bcChunk=64, t=255), Block: 32 threads.
// ---------------------------------------------------------------------------
__global__ __launch_bounds__(32)
void ring_idft_kernel(float* __restrict__ out)
{
    const int t   = blockIdx.y;
    const int bc0 = blockIdx.x * 4;
    const int tid = threadIdx.x;

    // HEALPix ring geometry (nside = 64)
    int n, roff;
    if (t <= 62)       { n = 4 * (t + 1); roff = 2 * t * (t + 1); }
    else if (t <= 191) { n = 256;         roff = 8064 + 256 * (t - 63); }
    else               { const int w = 255 - t; n = 4 * w; roff = NPIX - 2 * w * (w + 1); }

    const int nh   = n >> 1;
    const int n4   = n >> 2;
    const int kend = (nh - 1 < MM - 1) ? (nh - 1) : (MM - 1);
    const int kmax = (nh < MM - 1) ? nh : (MM - 1);

    __shared__ __align__(16) float sr4[MM * 4];
    __shared__ __align__(16) float si4[MM * 4];

    for (int idx = tid; idx < (kmax + 1) * 4; idx += 32) {
        const int mm = idx >> 2;
        const int b  = idx & 3;
        const size_t g = ((size_t)(bc0 + b) * MM + mm) * TLAT + t;
        sr4[idx] = g_re[g];
        si4[idx] = g_im[g];
    }
    __syncthreads();

    const int j0 = 2 * tid;
    if (j0 >= n4) return;
    const int j1 = j0 + 1;
    const bool a1 = (j1 < n4);

    // Accumulator pairs: [chain j][residue] x {bc01, bc23}
    ull U0a0, U0b0, U1a0, U1b0, U2a0, U2b0, U3a0, U3b0, V1a0, V1b0, V3a0, V3b0;
    ull U0a1, U0b1, U1a1, U1b1, U2a1, U2b1, U3a1, U3b1, V1a1, V1b1, V3a1, V3b1;

    {   // bin 0 -> U0 (same for both chains): 0.5 * re
        const ulonglong2 rp = *(const ulonglong2*)(sr4);
        const ull half = pack2(0.5f, 0.5f);
        U0a0 = fma2(rp.x, half, 0ull);
        U0b0 = fma2(rp.y, half, 0ull);
        U0a1 = U0a0; U0b1 = U0b0;
    }
    U1a0=U1b0=U2a0=U2b0=U3a0=U3b0=V1a0=V1b0=V3a0=V3b0=0ull;
    U1a1=U1b1=U2a1=U2b1=U3a1=U3b1=V1a1=V1b1=V3a1=V3b1=0ull;

    // Twiddle chains: step_j = e^{i*2*pi*j/n}; current value starts at k=1.
    const float tstep = 6.283185307179586f / (float)n;
    float stc0, sts0, stc1, sts1;
    sincosf(tstep * (float)j0, &sts0, &stc0);
    sincosf(tstep * (float)j1, &sts1, &stc1);
    float ca = stc0, sa = sts0;   // chain j0 current
    float cb = stc1, sb = sts1;   // chain j1 current

    #define LOADK(K)                                                        \
        const ulonglong2 rp = *(const ulonglong2*)(sr4 + (K) * 4);          \
        const ulonglong2 ip = *(const ulonglong2*)(si4 + (K) * 4);

    // U += re*c - im*s   (both chains)
    #define ACC_U2(K, A0, B0, A1, B1)                                       \
    {                                                                       \
        LOADK(K)                                                            \
        {                                                                   \
            const ull cc = pack2(ca, ca), ns = pack2(-sa, -sa);             \
            A0 = fma2(rp.x, cc, A0); A0 = fma2(ip.x, ns, A0);               \
            B0 = fma2(rp.y, cc, B0); B0 = fma2(ip.y, ns, B0);               \
        }                                                                   \
        {                                                                   \
            const ull cc = pack2(cb, cb), ns = pack2(-sb, -sb);             \
            A1 = fma2(rp.x, cc, A1); A1 = fma2(ip.x, ns, A1);               \
            B1 = fma2(rp.y, cc, B1); B1 = fma2(ip.y, ns, B1);               \
        }                                                                   \
    }
    // U += re*c - im*s ; V += re*s + im*c  (both chains)
    #define ACC_UV2(K, A0, B0, VA0, VB0, A1, B1, VA1, VB1)                  \
    {                                                                       \
        LOADK(K)                                                            \
        {                                                                   \
            const ull cc = pack2(ca, ca), ns = pack2(-sa, -sa), ss = pack2(sa, sa); \
            A0  = fma2(rp.x, cc, A0);  A0  = fma2(ip.x, ns, A0);            \
            B0  = fma2(rp.y, cc, B0);  B0  = fma2(ip.y, ns, B0);            \
            VA0 = fma2(rp.x, ss, VA0); VA0 = fma2(ip.x, cc, VA0);           \
            VB0 = fma2(rp.y, ss, VB0); VB0 = fma2(ip.y, cc, VB0);           \
        }                                                                   \
        {                                                                   \
            const ull cc = pack2(cb, cb), ns = pack2(-sb, -sb), ss = pack2(sb, sb); \
            A1  = fma2(rp.x, cc, A1);  A1  = fma2(ip.x, ns, A1);            \
            B1  = fma2(rp.y, cc, B1);  B1  = fma2(ip.y, ns, B1);            \
            VA1 = fma2(rp.x, ss, VA1); VA1 = fma2(ip.x, cc, VA1);           \
            VB1 = fma2(rp.y, ss, VB1); VB1 = fma2(ip.y, cc, VB1);           \
        }                                                                   \
    }
    #define ROT2()                                                          \
    {                                                                       \
        const float na = fmaf(ca, stc0, -sa * sts0);                        \
        const float ma = fmaf(sa, stc0,  ca * sts0);                        \
        ca = na; sa = ma;                                                   \
        const float nb = fmaf(cb, stc1, -sb * sts1);                        \
        const float mb = fmaf(sb, stc1,  cb * sts1);                        \
        cb = nb; sb = mb;                                                   \
    }

    int k = 1;
    for (; k + 3 <= kend; k += 4) {
        ACC_UV2(k,     U1a0,U1b0,V1a0,V1b0, U1a1,U1b1,V1a1,V1b1) ROT2()
        ACC_U2 (k + 1, U2a0,U2b0, U2a1,U2b1)                     ROT2()
        ACC_UV2(k + 2, U3a0,U3b0,V3a0,V3b0, U3a1,U3b1,V3a1,V3b1) ROT2()
        ACC_U2 (k + 3, U0a0,U0b0, U0a1,U0b1)                     ROT2()
    }
    for (; k <= kend; ++k) {
        const int r = k & 3;
        if (r == 1)      { ACC_UV2(k, U1a0,U1b0,V1a0,V1b0, U1a1,U1b1,V1a1,V1b1) }
        else if (r == 2) { ACC_U2 (k, U2a0,U2b0, U2a1,U2b1) }
        else if (r == 3) { ACC_UV2(k, U3a0,U3b0,V3a0,V3b0, U3a1,U3b1,V3a1,V3b1) }
        else             { ACC_U2 (k, U0a0,U0b0, U0a1,U0b1) }
        ROT2()
    }
    #undef LOADK
    #undef ACC_U2
    #undef ACC_UV2
    #undef ROT2

    // Nyquist weights (exists within 96 bins only when nh < 96)
    float w[4] = {0.f, 0.f, 0.f, 0.f};
    if (nh < MM) {
        w[0] = 0.5f * sr4[nh * 4 + 0];
        w[1] = 0.5f * sr4[nh * 4 + 1];
        w[2] = 0.5f * sr4[nh * 4 + 2];
        w[3] = 0.5f * sr4[nh * 4 + 3];
    }

    // Unpack accumulators into per-bc combos and emit 4 q-outputs per chain.
    float u0[2][4], u1[2][4], u2[2][4], u3[2][4], v1[2][4], v3[2][4];
    unpack2(U0a0, u0[0][0], u0[0][1]); unpack2(U0b0, u0[0][2], u0[0][3]);
    unpack2(U1a0, u1[0][0], u1[0][1]); unpack2(U1b0, u1[0][2], u1[0][3]);
    unpack2(U2a0, u2[0][0], u2[0][1]); unpack2(U2b0, u2[0][2], u2[0][3]);
    unpack2(U3a0, u3[0][0], u3[0][1]); unpack2(U3b0, u3[0][2], u3[0][3]);
    unpack2(V1a0, v1[0][0], v1[0][1]); unpack2(V1b0, v1[0][2], v1[0][3]);
    unpack2(V3a0, v3[0][0], v3[0][1]); unpack2(V3b0, v3[0][2], v3[0][3]);
    unpack2(U0a1, u0[1][0], u0[1][1]); unpack2(U0b1, u0[1][2], u0[1][3]);
    unpack2(U1a1, u1[1][0], u1[1][1]); unpack2(U1b1, u1[1][2], u1[1][3]);
    unpack2(U2a1, u2[1][0], u2[1][1]); unpack2(U2b1, u2[1][2], u2[1][3]);
    unpack2(U3a1, u3[1][0], u3[1][1]); unpack2(U3b1, u3[1][2], u3[1][3]);
    unpack2(V1a1, v1[1][0], v1[1][1]); unpack2(V1b1, v1[1][2], v1[1][3]);
    unpack2(V3a1, v3[1][0], v3[1][1]); unpack2(V3b1, v3[1][2], v3[1][3]);

    // y[jj][q][b]
    float y[2][4][4];
    #pragma unroll
    for (int jj = 0; jj < 2; ++jj) {
        #pragma unroll
        for (int b = 0; b < 4; ++b) {
            const float P  = u0[jj][b] + u2[jj][b];
            const float Md = u0[jj][b] - u2[jj][b];
            const float Cc = u1[jj][b] + u3[jj][b];
            const float Dd = v1[jj][b] - v3[jj][b];
            y[jj][0][b] = P + Cc;
            y[jj][1][b] = Md - Dd;
            y[jj][2][b] = P - Cc;
            y[jj][3][b] = Md + Dd;
        }
    }

    const size_t obase = (size_t)bc0 * NPIX + roff;
    if ((n4 & 1) == 0) {
        // n4 even: j0 even, j1 odd; p parity = j parity for every q.
        // j0 -> sign +1, j1 -> sign -1. Paired float2 stores, fully coalesced.
        #pragma unroll
        for (int q = 0; q < 4; ++q) {
            #pragma unroll
            for (int b = 0; b < 4; ++b) {
                const float2 val = make_float2(y[0][q][b] + w[b],
                                               y[1][q][b] - w[b]);
                *(float2*)(out + obase + (size_t)b * NPIX + q * n4 + j0) = val;
            }
        }
    } else {
        #pragma unroll
        for (int q = 0; q < 4; ++q) {
            const int p0 = j0 + q * n4;
            const float sg0 = (p0 & 1) ? -1.0f : 1.0f;
            #pragma unroll
            for (int b = 0; b < 4; ++b)
                out[obase + (size_t)b * NPIX + p0] = fmaf(sg0, w[b], y[0][q][b]);
            if (a1) {
                const float sg1 = -sg0;
                #pragma unroll
                for (int b = 0; b < 4; ++b)
                    out[obase + (size_t)b * NPIX + p0 + 1] = fmaf(sg1, w[b], y[1][q][b]);
            }
        }
    }
}

// ---------------------------------------------------------------------------
extern "C" void kernel_launch(void* const* d_in, const int* in_sizes, int n_in,
                              void* d_out, int out_size)
{
    const float* xr  = (const float*)d_in[0];  // (4,64,96,96)
    const float* xi  = (const float*)d_in[1];  // (4,64,96,96)
    const float* pct = (const float*)d_in[2];  // (96,96,255)
    const float* off = (const float*)d_in[3];  // (255,96)
    float* out = (float*)d_out;                // (4,64,49152)

    {
        dim3 grid(MM, BC / 8);     // 96 x 32
        legendre_phase_kernel<<<grid, 64>>>(xr, xi, pct, off);
    }
    {
        dim3 grid(BC / 4, TLAT);   // 64 x 255
        ring_idft_kernel<<<grid, 32>>>(out);
    }
}

// round 7
// speedup vs baseline: 1.8268x; 1.0341x over previous
#include <cuda_runtime.h>
#include <math.h>

// Problem constants
#define MM    96      // MMAX
#define LLM   96      // LMAX
#define TLAT  255     // NLAT = 4*64-1
#define BC    256     // B*C = 4*64
#define NPIX  49152   // 12 * 64^2

typedef unsigned long long ull;

// ---- f32x2 packed math helpers (Blackwell FFMA2) --------------------------
__device__ __forceinline__ ull pack2(float lo, float hi) {
    ull r; asm("mov.b64 %0, {%1, %2};" : "=l"(r) : "f"(lo), "f"(hi)); return r;
}
__device__ __forceinline__ void unpack2(ull v, float& lo, float& hi) {
    asm("mov.b64 {%0, %1}, %2;" : "=f"(lo), "=f"(hi) : "l"(v));
}
__device__ __forceinline__ ull fma2(ull a, ull b, ull c) {
    ull d; asm("fma.rn.f32x2 %0, %1, %2, %3;" : "=l"(d) : "l"(a), "l"(b), "l"(c)); return d;
}

// Scratch: phase-rotated spectral coefficients, pre-scaled by 2 (irfft weight).
// Layout [bc][m][t] so kernel A stores are coalesced along t(=k).
__device__ float g_re[BC * MM * TLAT];
__device__ float g_im[BC * MM * TLAT];

// ---------------------------------------------------------------------------
// Kernel A: rl[bc,k,m] = sum_l x[bc,l,m] * pct[m,l,k], then multiply by
// exp(i*offset[k,m]), scale by 2, store to g_re/g_im in [bc][m][k] layout.
// 2 rings per thread (k, k+128); smem holds (re,im) interleaved so one
// ulonglong2 load yields two f32x2 operands; pct software-prefetched.
// Grid: (m=96, bcChunk=32), Block: 128 threads.  BCC = 8.
// ---------------------------------------------------------------------------
__global__ __launch_bounds__(128)
void legendre_phase_kernel(const float* __restrict__ xr,
                           const float* __restrict__ xi,
                           const float* __restrict__ pct,
                           const float* __restrict__ off)
{
    const int m   = blockIdx.x;
    const int bc0 = blockIdx.y * 8;
    const int tid = threadIdx.x;

    __shared__ __align__(16) float2 sx[LLM * 8];   // (re,im) pairs, [l][b]

    for (int idx = tid; idx < LLM * 8; idx += 128) {
        const int l = idx >> 3;
        const int b = idx & 7;
        const int g = ((bc0 + b) * LLM + l) * MM + m;
        sx[idx] = make_float2(xr[g], xi[g]);
    }
    __syncthreads();

    const int k0  = tid;          // 0..127
    const int k1r = tid + 128;    // 128..255
    const bool has1 = (k1r < TLAT);
    const int k1  = has1 ? k1r : (TLAT - 1);  // clamped (result discarded)

    ull acc0[8], acc1[8];
    #pragma unroll
    for (int b = 0; b < 8; ++b) { acc0[b] = 0ull; acc1[b] = 0ull; }

    const float* __restrict__ pm = pct + (size_t)m * LLM * TLAT;

    // software prefetch of pct rows (one l ahead)
    float p0 = pm[k0];
    float p1 = pm[k1];

    #pragma unroll 2
    for (int l = 0; l < LLM; ++l) {
        const ull pp0 = pack2(p0, p0);
        const ull pp1 = pack2(p1, p1);
        if (l + 1 < LLM) {
            const float* __restrict__ pr = pm + (size_t)(l + 1) * TLAT;
            p0 = pr[k0];
            p1 = pr[k1];
        }
        const ulonglong2* __restrict__ row = (const ulonglong2*)(sx + l * 8);
        const ulonglong2 v0 = row[0];   // (re,im) for bc0, bc1
        const ulonglong2 v1 = row[1];   // bc2, bc3
        const ulonglong2 v2 = row[2];   // bc4, bc5
        const ulonglong2 v3 = row[3];   // bc6, bc7
        acc0[0] = fma2(v0.x, pp0, acc0[0]);  acc1[0] = fma2(v0.x, pp1, acc1[0]);
        acc0[1] = fma2(v0.y, pp0, acc0[1]);  acc1[1] = fma2(v0.y, pp1, acc1[1]);
        acc0[2] = fma2(v1.x, pp0, acc0[2]);  acc1[2] = fma2(v1.x, pp1, acc1[2]);
        acc0[3] = fma2(v1.y, pp0, acc0[3]);  acc1[3] = fma2(v1.y, pp1, acc1[3]);
        acc0[4] = fma2(v2.x, pp0, acc0[4]);  acc1[4] = fma2(v2.x, pp1, acc1[4]);
        acc0[5] = fma2(v2.y, pp0, acc0[5]);  acc1[5] = fma2(v2.y, pp1, acc1[5]);
        acc0[6] = fma2(v3.x, pp0, acc0[6]);  acc1[6] = fma2(v3.x, pp1, acc1[6]);
        acc0[7] = fma2(v3.y, pp0, acc0[7]);  acc1[7] = fma2(v3.y, pp1, acc1[7]);
    }

    {   // ring k0
        float sa, ca;
        sincosf(off[k0 * MM + m], &sa, &ca);
        #pragma unroll
        for (int b = 0; b < 8; ++b) {
            float ar, ai;
            unpack2(acc0[b], ar, ai);
            const size_t o = ((size_t)(bc0 + b) * MM + m) * TLAT + k0;
            g_re[o] = 2.0f * (ar * ca - ai * sa);
            g_im[o] = 2.0f * (ar * sa + ai * ca);
        }
    }
    if (has1) {   // ring k1
        float sa, ca;
        sincosf(off[k1 * MM + m], &sa, &ca);
        #pragma unroll
        for (int b = 0; b < 8; ++b) {
            float ar, ai;
            unpack2(acc1[b], ar, ai);
            const size_t o = ((size_t)(bc0 + b) * MM + m) * TLAT + k1;
            g_re[o] = 2.0f * (ar * ca - ai * sa);
            g_im[o] = 2.0f * (ar * sa + ai * ca);
        }
    }
}

// ---------------------------------------------------------------------------
// Kernel B: per-ring inverse real DFT (norm='forward', n % 4 == 0).
// Quarter-wave split + j-pairing: thread handles j0=2*tid and j1=j0+1, each
// producing 4 outputs p = j + q*(n/4) via residue accumulators:
//   y(j)      = (U0+U2) + (U1+U3)
//   y(j+n/4)  = (U0-U2) - (V1-V3)
//   y(j+n/2)  = (U0+U2) - (U1+U3)
//   y(j+3n/4) = (U0-U2) + (V1-V3)
// BCC = 4 bc lanes per block, packed as two f32x2 pairs.
// Stored coefficients pre-scaled by 2, so bin0/Nyquist use factor 0.5.
// Grid: (bcChunk=64, t=255), Block: 32 threads.
// ---------------------------------------------------------------------------
__global__ __launch_bounds__(32)
void ring_idft_kernel(float* __restrict__ out)
{
    const int t   = blockIdx.y;
    const int bc0 = blockIdx.x * 4;
    const int tid = threadIdx.x;

    // HEALPix ring geometry (nside = 64)
    int n, roff;
    if (t <= 62)       { n = 4 * (t + 1); roff = 2 * t * (t + 1); }
    else if (t <= 191) { n = 256;         roff = 8064 + 256 * (t - 63); }
    else               { const int w = 255 - t; n = 4 * w; roff = NPIX - 2 * w * (w + 1); }

    const int nh   = n >> 1;
    const int n4   = n >> 2;
    const int kend = (nh - 1 < MM - 1) ? (nh - 1) : (MM - 1);
    const int kmax = (nh < MM - 1) ? nh : (MM - 1);

    __shared__ __align__(16) float sr4[MM * 4];
    __shared__ __align__(16) float si4[MM * 4];

    for (int idx = tid; idx < (kmax + 1) * 4; idx += 32) {
        const int mm = idx >> 2;
        const int b  = idx & 3;
        const size_t g = ((size_t)(bc0 + b) * MM + mm) * TLAT + t;
        sr4[idx] = g_re[g];
        si4[idx] = g_im[g];
    }
    __syncthreads();

    const int j0 = 2 * tid;
    if (j0 >= n4) return;
    const int j1 = j0 + 1;
    const bool a1 = (j1 < n4);

    // Accumulator pairs: [chain j][residue] x {bc01, bc23}
    ull U0a0, U0b0, U1a0, U1b0, U2a0, U2b0, U3a0, U3b0, V1a0, V1b0, V3a0, V3b0;
    ull U0a1, U0b1, U1a1, U1b1, U2a1, U2b1, U3a1, U3b1, V1a1, V1b1, V3a1, V3b1;

    {   // bin 0 -> U0 (same for both chains): 0.5 * re
        const ulonglong2 rp = *(const ulonglong2*)(sr4);
        const ull half = pack2(0.5f, 0.5f);
        U0a0 = fma2(rp.x, half, 0ull);
        U0b0 = fma2(rp.y, half, 0ull);
        U0a1 = U0a0; U0b1 = U0b0;
    }
    U1a0=U1b0=U2a0=U2b0=U3a0=U3b0=V1a0=V1b0=V3a0=V3b0=0ull;
    U1a1=U1b1=U2a1=U2b1=U3a1=U3b1=V1a1=V1b1=V3a1=V3b1=0ull;

    // Twiddle chains: step_j = e^{i*2*pi*j/n}; current value starts at k=1.
    const float tstep = 6.283185307179586f / (float)n;
    float stc0, sts0, stc1, sts1;
    sincosf(tstep * (float)j0, &sts0, &stc0);
    sincosf(tstep * (float)j1, &sts1, &stc1);
    float ca = stc0, sa = sts0;   // chain j0 current
    float cb = stc1, sb = sts1;   // chain j1 current

    #define LOADK(K)                                                        \
        const ulonglong2 rp = *(const ulonglong2*)(sr4 + (K) * 4);          \
        const ulonglong2 ip = *(const ulonglong2*)(si4 + (K) * 4);

    // U += re*c - im*s   (both chains)
    #define ACC_U2(K, A0, B0, A1, B1)                                       \
    {                                                                       \
        LOADK(K)                                                            \
        {                                                                   \
            const ull cc = pack2(ca, ca), ns = pack2(-sa, -sa);             \
            A0 = fma2(rp.x, cc, A0); A0 = fma2(ip.x, ns, A0);               \
            B0 = fma2(rp.y, cc, B0); B0 = fma2(ip.y, ns, B0);               \
        }                                                                   \
        {                                                                   \
            const ull cc = pack2(cb, cb), ns = pack2(-sb, -sb);             \
            A1 = fma2(rp.x, cc, A1); A1 = fma2(ip.x, ns, A1);               \
            B1 = fma2(rp.y, cc, B1); B1 = fma2(ip.y, ns, B1);               \
        }                                                                   \
    }
    // U += re*c - im*s ; V += re*s + im*c  (both chains)
    #define ACC_UV2(K, A0, B0, VA0, VB0, A1, B1, VA1, VB1)                  \
    {                                                                       \
        LOADK(K)                                                            \
        {                                                                   \
            const ull cc = pack2(ca, ca), ns = pack2(-sa, -sa), ss = pack2(sa, sa); \
            A0  = fma2(rp.x, cc, A0);  A0  = fma2(ip.x, ns, A0);            \
            B0  = fma2(rp.y, cc, B0);  B0  = fma2(ip.y, ns, B0);            \
            VA0 = fma2(rp.x, ss, VA0); VA0 = fma2(ip.x, cc, VA0);           \
            VB0 = fma2(rp.y, ss, VB0); VB0 = fma2(ip.y, cc, VB0);           \
        }                                                                   \
        {                                                                   \
            const ull cc = pack2(cb, cb), ns = pack2(-sb, -sb), ss = pack2(sb, sb); \
            A1  = fma2(rp.x, cc, A1);  A1  = fma2(ip.x, ns, A1);            \
            B1  = fma2(rp.y, cc, B1);  B1  = fma2(ip.y, ns, B1);            \
            VA1 = fma2(rp.x, ss, VA1); VA1 = fma2(ip.x, cc, VA1);           \
            VB1 = fma2(rp.y, ss, VB1); VB1 = fma2(ip.y, cc, VB1);           \
        }                                                                   \
    }
    #define ROT2()                                                          \
    {                                                                       \
        const float na = fmaf(ca, stc0, -sa * sts0);                        \
        const float ma = fmaf(sa, stc0,  ca * sts0);                        \
        ca = na; sa = ma;                                                   \
        const float nb = fmaf(cb, stc1, -sb * sts1);                        \
        const float mb = fmaf(sb, stc1,  cb * sts1);                        \
        cb = nb; sb = mb;                                                   \
    }

    int k = 1;
    for (; k + 3 <= kend; k += 4) {
        ACC_UV2(k,     U1a0,U1b0,V1a0,V1b0, U1a1,U1b1,V1a1,V1b1) ROT2()
        ACC_U2 (k + 1, U2a0,U2b0, U2a1,U2b1)                     ROT2()
        ACC_UV2(k + 2, U3a0,U3b0,V3a0,V3b0, U3a1,U3b1,V3a1,V3b1) ROT2()
        ACC_U2 (k + 3, U0a0,U0b0, U0a1,U0b1)                     ROT2()
    }
    for (; k <= kend; ++k) {
        const int r = k & 3;
        if (r == 1)      { ACC_UV2(k, U1a0,U1b0,V1a0,V1b0, U1a1,U1b1,V1a1,V1b1) }
        else if (r == 2) { ACC_U2 (k, U2a0,U2b0, U2a1,U2b1) }
        else if (r == 3) { ACC_UV2(k, U3a0,U3b0,V3a0,V3b0, U3a1,U3b1,V3a1,V3b1) }
        else             { ACC_U2 (k, U0a0,U0b0, U0a1,U0b1) }
        ROT2()
    }
    #undef LOADK
    #undef ACC_U2
    #undef ACC_UV2
    #undef ROT2

    // Nyquist weights (exists within 96 bins only when nh < 96)
    float w[4] = {0.f, 0.f, 0.f, 0.f};
    if (nh < MM) {
        w[0] = 0.5f * sr4[nh * 4 + 0];
        w[1] = 0.5f * sr4[nh * 4 + 1];
        w[2] = 0.5f * sr4[nh * 4 + 2];
        w[3] = 0.5f * sr4[nh * 4 + 3];
    }

    // Unpack accumulators into per-bc combos and emit 4 q-outputs per chain.
    float u0[2][4], u1[2][4], u2[2][4], u3[2][4], v1[2][4], v3[2][4];
    unpack2(U0a0, u0[0][0], u0[0][1]); unpack2(U0b0, u0[0][2], u0[0][3]);
    unpack2(U1a0, u1[0][0], u1[0][1]); unpack2(U1b0, u1[0][2], u1[0][3]);
    unpack2(U2a0, u2[0][0], u2[0][1]); unpack2(U2b0, u2[0][2], u2[0][3]);
    unpack2(U3a0, u3[0][0], u3[0][1]); unpack2(U3b0, u3[0][2], u3[0][3]);
    unpack2(V1a0, v1[0][0], v1[0][1]); unpack2(V1b0, v1[0][2], v1[0][3]);
    unpack2(V3a0, v3[0][0], v3[0][1]); unpack2(V3b0, v3[0][2], v3[0][3]);
    unpack2(U0a1, u0[1][0], u0[1][1]); unpack2(U0b1, u0[1][2], u0[1][3]);
    unpack2(U1a1, u1[1][0], u1[1][1]); unpack2(U1b1, u1[1][2], u1[1][3]);
    unpack2(U2a1, u2[1][0], u2[1][1]); unpack2(U2b1, u2[1][2], u2[1][3]);
    unpack2(U3a1, u3[1][0], u3[1][1]); unpack2(U3b1, u3[1][2], u3[1][3]);
    unpack2(V1a1, v1[1][0], v1[1][1]); unpack2(V1b1, v1[1][2], v1[1][3]);
    unpack2(V3a1, v3[1][0], v3[1][1]); unpack2(V3b1, v3[1][2], v3[1][3]);

    // y[jj][q][b]
    float y[2][4][4];
    #pragma unroll
    for (int jj = 0; jj < 2; ++jj) {
        #pragma unroll
        for (int b = 0; b < 4; ++b) {
            const float P  = u0[jj][b] + u2[jj][b];
            const float Md = u0[jj][b] - u2[jj][b];
            const float Cc = u1[jj][b] + u3[jj][b];
            const float Dd = v1[jj][b] - v3[jj][b];
            y[jj][0][b] = P + Cc;
            y[jj][1][b] = Md - Dd;
            y[jj][2][b] = P - Cc;
            y[jj][3][b] = Md + Dd;
        }
    }

    const size_t obase = (size_t)bc0 * NPIX + roff;
    if ((n4 & 1) == 0) {
        // n4 even: j0 even, j1 odd; p parity = j parity for every q.
        // j0 -> sign +1, j1 -> sign -1. Paired float2 stores, fully coalesced.
        #pragma unroll
        for (int q = 0; q < 4; ++q) {
            #pragma unroll
            for (int b = 0; b < 4; ++b) {
                const float2 val = make_float2(y[0][q][b] + w[b],
                                               y[1][q][b] - w[b]);
                *(float2*)(out + obase + (size_t)b * NPIX + q * n4 + j0) = val;
            }
        }
    } else {
        #pragma unroll
        for (int q = 0; q < 4; ++q) {
            const int p0 = j0 + q * n4;
            const float sg0 = (p0 & 1) ? -1.0f : 1.0f;
            #pragma unroll
            for (int b = 0; b < 4; ++b)
                out[obase + (size_t)b * NPIX + p0] = fmaf(sg0, w[b], y[0][q][b]);
            if (a1) {
                const float sg1 = -sg0;
                #pragma unroll
                for (int b = 0; b < 4; ++b)
                    out[obase + (size_t)b * NPIX + p0 + 1] = fmaf(sg1, w[b], y[1][q][b]);
            }
        }
    }
}

// ---------------------------------------------------------------------------
extern "C" void kernel_launch(void* const* d_in, const int* in_sizes, int n_in,
                              void* d_out, int out_size)
{
    const float* xr  = (const float*)d_in[0];  // (4,64,96,96)
    const float* xi  = (const float*)d_in[1];  // (4,64,96,96)
    const float* pct = (const float*)d_in[2];  // (96,96,255)
    const float* off = (const float*)d_in[3];  // (255,96)
    float* out = (float*)d_out;                // (4,64,49152)

    {
        dim3 grid(MM, BC / 8);     // 96 x 32
        legendre_phase_kernel<<<grid, 128>>>(xr, xi, pct, off);
    }
    {
        dim3 grid(BC / 4, TLAT);   // 64 x 255
        ring_idft_kernel<<<grid, 32>>>(out);
    }
}